// round 1
// baseline (speedup 1.0000x reference)
#include <cuda_runtime.h>
#include <math.h>

#define LSEQ 256
#define BSZ  64
#define NH   8
#define DH   128
#define DM   1024
#define NQ   4096
#define MROWS (LSEQ*BSZ)
#define SCALE_F 0.08838834764831845f
#define LN_EPS_F 1e-5f

// ---- scratch (static device arrays; no allocation) ----
__device__ float g_qkv[(size_t)MROWS * NQ];   // [l*b, 4096] raw qkv, phi'd in place
__device__ float g_lo [(size_t)MROWS * DM];   // layer_out in [l, b, DM]
__device__ float g_x  [(size_t)MROWS * DM];   // h + attn_out

// ======================= GEMM: C[M,N] = A[M,K] * B[N,K]^T (+R) =======================
// MODE 0: A = param (h),  C = g_qkv, no residual
// MODE 1: A = g_lo,       C = g_x,   residual = param R (h)
template<int MODE>
__global__ void __launch_bounds__(256)
gemm_tn(const float* __restrict__ Aext, const float* __restrict__ Bm,
        const float* __restrict__ R, int M, int N, int K)
{
    const float* A = (MODE == 0) ? Aext : g_lo;
    float* C = (MODE == 0) ? g_qkv : g_x;

    __shared__ float As[16][132];
    __shared__ float Bs[16][132];
    const int tid = threadIdx.x;
    const int ty = tid >> 4, tx = tid & 15;
    const int m0 = blockIdx.y * 128, n0 = blockIdx.x * 128;
    const int lr = tid >> 2, lk = (tid & 3) << 2;

    float acc[8][8];
#pragma unroll
    for (int i = 0; i < 8; i++)
#pragma unroll
        for (int j = 0; j < 8; j++) acc[i][j] = 0.f;

    const float* Ap = A  + (size_t)(m0 + lr) * K + lk;
    const float* Bp = Bm + (size_t)(n0 + lr) * K + lk;

    for (int k0 = 0; k0 < K; k0 += 16) {
        float4 a0 = *(const float4*)(Ap + k0);
        float4 a1 = *(const float4*)(Ap + (size_t)64 * K + k0);
        float4 b0 = *(const float4*)(Bp + k0);
        float4 b1 = *(const float4*)(Bp + (size_t)64 * K + k0);
        As[lk+0][lr]    = a0.x; As[lk+1][lr]    = a0.y; As[lk+2][lr]    = a0.z; As[lk+3][lr]    = a0.w;
        As[lk+0][lr+64] = a1.x; As[lk+1][lr+64] = a1.y; As[lk+2][lr+64] = a1.z; As[lk+3][lr+64] = a1.w;
        Bs[lk+0][lr]    = b0.x; Bs[lk+1][lr]    = b0.y; Bs[lk+2][lr]    = b0.z; Bs[lk+3][lr]    = b0.w;
        Bs[lk+0][lr+64] = b1.x; Bs[lk+1][lr+64] = b1.y; Bs[lk+2][lr+64] = b1.z; Bs[lk+3][lr+64] = b1.w;
        __syncthreads();
#pragma unroll
        for (int kk = 0; kk < 16; kk++) {
            float a[8], b[8];
            float4 v0 = *(const float4*)&As[kk][ty*8];
            float4 v1 = *(const float4*)&As[kk][ty*8+4];
            float4 v2 = *(const float4*)&Bs[kk][tx*8];
            float4 v3 = *(const float4*)&Bs[kk][tx*8+4];
            a[0]=v0.x;a[1]=v0.y;a[2]=v0.z;a[3]=v0.w;a[4]=v1.x;a[5]=v1.y;a[6]=v1.z;a[7]=v1.w;
            b[0]=v2.x;b[1]=v2.y;b[2]=v2.z;b[3]=v2.w;b[4]=v3.x;b[5]=v3.y;b[6]=v3.z;b[7]=v3.w;
#pragma unroll
            for (int i = 0; i < 8; i++)
#pragma unroll
                for (int j = 0; j < 8; j++) acc[i][j] = fmaf(a[i], b[j], acc[i][j]);
        }
        __syncthreads();
    }

#pragma unroll
    for (int i = 0; i < 8; i++) {
        int m = m0 + ty*8 + i;
        float* crow = C + (size_t)m * N + n0 + tx*8;
#pragma unroll
        for (int jv = 0; jv < 8; jv += 4) {
            float4 v;
            v.x = acc[i][jv+0]; v.y = acc[i][jv+1]; v.z = acc[i][jv+2]; v.w = acc[i][jv+3];
            if (MODE == 1) {
                const float4 rr = *(const float4*)(R + (size_t)m * N + n0 + tx*8 + jv);
                v.x += rr.x; v.y += rr.y; v.z += rr.z; v.w += rr.w;
            }
            *(float4*)(crow + jv) = v;
        }
    }
}

// ======================= phi: elu(x)+1, then L1 normalize over 128-dim =======================
// one warp per (l,b,head,which) vector; which in {0=q,1=k1,2=k2}; in place on g_qkv
__global__ void __launch_bounds__(256) phi_kernel()
{
    int w = (blockIdx.x * 256 + threadIdx.x) >> 5;
    int lane = threadIdx.x & 31;
    int which = w % 3;
    int lbh = w / 3;   // (l*BSZ + b)*NH + head
    size_t base = (size_t)(lbh >> 3) * NQ + (size_t)((lbh & 7) * 512 + which * 128);
    float4 x = *(float4*)&g_qkv[base + lane * 4];
    x.x = (x.x > 0.f) ? x.x + 1.f : expf(x.x);
    x.y = (x.y > 0.f) ? x.y + 1.f : expf(x.y);
    x.z = (x.z > 0.f) ? x.z + 1.f : expf(x.z);
    x.w = (x.w > 0.f) ? x.w + 1.f : expf(x.w);
    float s = x.x + x.y + x.z + x.w;
#pragma unroll
    for (int o = 16; o > 0; o >>= 1) s += __shfl_xor_sync(0xffffffffu, s, o);
    float inv = 1.f / s;
    x.x *= inv; x.y *= inv; x.z *= inv; x.w *= inv;
    *(float4*)&g_qkv[base + lane * 4] = x;
}

// ======================= fused dual causal linear attention =======================
// block: (t_tile 0..3, bh 0..511), 256 threads. P = pi*Q.K1^T + (1-pi)*Q.K2^T (masked),
// acc += P.V, out = SCALE*acc written in [l, b, DM] layout.
#define ATTN_SMEM_FLOATS (3*128*68 + 64*132 + 64*68)
#define ATTN_SMEM_BYTES (ATTN_SMEM_FLOATS * 4)

__global__ void __launch_bounds__(256)
attn_kernel(const float* __restrict__ pi0)
{
    extern __shared__ float sm[];
    float* Qs  = sm;                    // [128 d][68] (transposed, col = t)
    float* K1s = Qs  + 128*68;
    float* K2s = K1s + 128*68;
    float* Vs  = K2s + 128*68;          // [64 s][132] (natural, col = d)
    float* Ps  = Vs  + 64*132;          // [64 s][68]  (col = t)

    const int tid = threadIdx.x;
    const int ty = tid >> 4, tx = tid & 15;
    const int tt = blockIdx.x;
    const int bh = blockIdx.y;
    const int b  = bh >> 3, head = bh & 7;
    const int t0 = tt * 64;

    // load Q tile transposed
#pragma unroll
    for (int p = 0; p < 8; p++) {
        int idx = tid + p * 256;
        int row = idx >> 5, d = (idx & 31) << 2;
        float4 q = *(const float4*)&g_qkv[((size_t)(t0 + row) * BSZ + b) * NQ + head * 512 + d];
        Qs[(d+0)*68 + row] = q.x; Qs[(d+1)*68 + row] = q.y;
        Qs[(d+2)*68 + row] = q.z; Qs[(d+3)*68 + row] = q.w;
    }

    float pclip[4];
#pragma unroll
    for (int i = 0; i < 4; i++) {
        float p = pi0[head * 256 + t0 + ty*4 + i];
        pclip[i] = fminf(fmaxf(p, 0.f), 1.f);
    }

    float acc[4][8];
#pragma unroll
    for (int i = 0; i < 4; i++)
#pragma unroll
        for (int j = 0; j < 8; j++) acc[i][j] = 0.f;

    for (int st = 0; st <= tt; st++) {
        const int s0 = st * 64;
        if (st > 0) __syncthreads();   // prior PV reads done before overwriting tiles
#pragma unroll
        for (int p = 0; p < 8; p++) {
            int idx = tid + p * 256;
            int row = idx >> 5, d = (idx & 31) << 2;
            size_t base = ((size_t)(s0 + row) * BSZ + b) * NQ + head * 512;
            float4 k1 = *(const float4*)&g_qkv[base + 128 + d];
            float4 k2 = *(const float4*)&g_qkv[base + 256 + d];
            float4 vv = *(const float4*)&g_qkv[base + 384 + d];
            K1s[(d+0)*68+row]=k1.x; K1s[(d+1)*68+row]=k1.y; K1s[(d+2)*68+row]=k1.z; K1s[(d+3)*68+row]=k1.w;
            K2s[(d+0)*68+row]=k2.x; K2s[(d+1)*68+row]=k2.y; K2s[(d+2)*68+row]=k2.z; K2s[(d+3)*68+row]=k2.w;
            *(float4*)&Vs[row*132 + d] = vv;
        }
        __syncthreads();

        float p1[4][4], p2[4][4];
#pragma unroll
        for (int i = 0; i < 4; i++)
#pragma unroll
            for (int j = 0; j < 4; j++) { p1[i][j] = 0.f; p2[i][j] = 0.f; }

#pragma unroll 4
        for (int d = 0; d < 128; d++) {
            float4 qa = *(const float4*)&Qs[d*68 + ty*4];
            float4 ka = *(const float4*)&K1s[d*68 + tx*4];
            float4 kb = *(const float4*)&K2s[d*68 + tx*4];
            float qv[4]  = {qa.x, qa.y, qa.z, qa.w};
            float k1v[4] = {ka.x, ka.y, ka.z, ka.w};
            float k2v[4] = {kb.x, kb.y, kb.z, kb.w};
#pragma unroll
            for (int i = 0; i < 4; i++)
#pragma unroll
                for (int j = 0; j < 4; j++) {
                    p1[i][j] = fmaf(qv[i], k1v[j], p1[i][j]);
                    p2[i][j] = fmaf(qv[i], k2v[j], p2[i][j]);
                }
        }

        const bool diag = (st == tt);
#pragma unroll
        for (int i = 0; i < 4; i++)
#pragma unroll
            for (int j = 0; j < 4; j++) {
                float v = pclip[i]*p1[i][j] + (1.f - pclip[i])*p2[i][j];
                if (diag && (tx*4 + j) > (ty*4 + i)) v = 0.f;   // s > t on diagonal tile
                Ps[(tx*4 + j)*68 + (ty*4 + i)] = v;
            }
        __syncthreads();

#pragma unroll 8
        for (int s = 0; s < 64; s++) {
            float4 pa = *(const float4*)&Ps[s*68 + ty*4];
            float4 v0 = *(const float4*)&Vs[s*132 + tx*8];
            float4 v1 = *(const float4*)&Vs[s*132 + tx*8 + 4];
            float pv[4] = {pa.x, pa.y, pa.z, pa.w};
            float vv[8] = {v0.x, v0.y, v0.z, v0.w, v1.x, v1.y, v1.z, v1.w};
#pragma unroll
            for (int i = 0; i < 4; i++)
#pragma unroll
                for (int j = 0; j < 8; j++) acc[i][j] = fmaf(pv[i], vv[j], acc[i][j]);
        }
    }

#pragma unroll
    for (int i = 0; i < 4; i++) {
        int t = t0 + ty*4 + i;
        float* dst = &g_lo[((size_t)t * BSZ + b) * DM + head*DH + tx*8];
        float4 o;
        o.x = SCALE_F*acc[i][0]; o.y = SCALE_F*acc[i][1]; o.z = SCALE_F*acc[i][2]; o.w = SCALE_F*acc[i][3];
        *(float4*)dst = o;
        o.x = SCALE_F*acc[i][4]; o.y = SCALE_F*acc[i][5]; o.z = SCALE_F*acc[i][6]; o.w = SCALE_F*acc[i][7];
        *(float4*)(dst + 4) = o;
    }
}

// ======================= LayerNorm: one block per row of 1024 =======================
__global__ void __launch_bounds__(256)
ln_kernel(const float* __restrict__ gamma, const float* __restrict__ beta,
          float* __restrict__ out)
{
    __shared__ float red[8];
    const int r = blockIdx.x, tid = threadIdx.x;
    const int lane = tid & 31, wid = tid >> 5;
    float4 v = *(const float4*)&g_x[(size_t)r * DM + tid * 4];
    float s = v.x + v.y + v.z + v.w;
#pragma unroll
    for (int o = 16; o > 0; o >>= 1) s += __shfl_xor_sync(0xffffffffu, s, o);
    if (lane == 0) red[wid] = s;
    __syncthreads();
    float tot = 0.f;
#pragma unroll
    for (int i = 0; i < 8; i++) tot += red[i];
    float mu = tot * (1.f / DM);
    float d0 = v.x - mu, d1 = v.y - mu, d2 = v.z - mu, d3 = v.w - mu;
    float sq = d0*d0 + d1*d1 + d2*d2 + d3*d3;
#pragma unroll
    for (int o = 16; o > 0; o >>= 1) sq += __shfl_xor_sync(0xffffffffu, sq, o);
    __syncthreads();
    if (lane == 0) red[wid] = sq;
    __syncthreads();
    float tot2 = 0.f;
#pragma unroll
    for (int i = 0; i < 8; i++) tot2 += red[i];
    float inv = rsqrtf(tot2 * (1.f / DM) + LN_EPS_F);
    float4 g = *(const float4*)&gamma[tid * 4];
    float4 bt = *(const float4*)&beta[tid * 4];
    float4 o;
    o.x = g.x * d0 * inv + bt.x;
    o.y = g.y * d1 * inv + bt.y;
    o.z = g.z * d2 * inv + bt.z;
    o.w = g.w * d3 * inv + bt.w;
    *(float4*)&out[(size_t)r * DM + tid * 4] = o;
}

// ======================= launch =======================
extern "C" void kernel_launch(void* const* d_in, const int* in_sizes, int n_in,
                              void* d_out, int out_size)
{
    const float* h     = (const float*)d_in[0];
    const float* Wqkv  = (const float*)d_in[1];
    const float* Wo    = (const float*)d_in[2];
    const float* pi0   = (const float*)d_in[3];
    const float* gamma = (const float*)d_in[4];
    const float* beta  = (const float*)d_in[5];
    float* out = (float*)d_out;

    // 1. qkv = h @ Wqkv^T   [16384 x 4096]
    gemm_tn<0><<<dim3(NQ/128, MROWS/128), 256>>>(h, Wqkv, nullptr, MROWS, NQ, DM);

    // 2. phi on q, k1, k2 (in place)
    phi_kernel<<<(MROWS * NH * 3) / 8, 256>>>();

    // 3. fused dual causal linear attention -> g_lo [l, b, DM]
    cudaFuncSetAttribute(attn_kernel, cudaFuncAttributeMaxDynamicSharedMemorySize, ATTN_SMEM_BYTES);
    attn_kernel<<<dim3(LSEQ/64, BSZ*NH), 256, ATTN_SMEM_BYTES>>>(pi0);

    // 4. x = g_lo @ Wo^T + h   [16384 x 1024]
    gemm_tn<1><<<dim3(DM/128, MROWS/128), 256>>>(nullptr, Wo, h, MROWS, DM, DM);

    // 5. LayerNorm -> out
    ln_kernel<<<MROWS, 256>>>(gamma, beta, out);
}

// round 4
// speedup vs baseline: 1.9738x; 1.9738x over previous
#include <cuda_runtime.h>
#include <cstdint>
#include <math.h>

#define LSEQ 256
#define BSZ  64
#define NH   8
#define DH   128
#define DM   1024
#define NQ   4096
#define MROWS (LSEQ*BSZ)
#define SCALE_F 0.08838834764831845f
#define LN_EPS_F 1e-5f

// ---- scratch (static device arrays; no allocation) ----
__device__ float g_qkv[(size_t)MROWS * NQ];   // [l*b, 4096] qkv, phi applied to q,k1,k2
__device__ float g_lo [(size_t)MROWS * DM];   // layer_out [l, b, DM] (tf32-rounded)
__device__ float g_x  [(size_t)MROWS * DM];   // h + attn_out
__device__ float g_hr [(size_t)MROWS * DM];   // h rounded to tf32
__device__ float g_wq [(size_t)NQ * DM];      // Wqkv rounded to tf32
__device__ float g_wo [(size_t)DM * DM];      // Wo rounded to tf32

// ======================= helpers =======================
__device__ __forceinline__ uint32_t smem_u32(const void* p) {
    uint32_t a;
    asm("{ .reg .u64 t; cvta.to.shared.u64 t, %1; cvt.u32.u64 %0, t; }" : "=r"(a) : "l"(p));
    return a;
}
__device__ __forceinline__ float rnd_tf32(float x) {
    uint32_t u;
    asm("cvt.rna.tf32.f32 %0, %1;" : "=r"(u) : "f"(x));
    return __uint_as_float(u);
}
__device__ __forceinline__ void cp16(float* s, const float* g) {
    uint32_t sa = smem_u32(s);
    asm volatile("cp.async.cg.shared.global [%0], [%1], 16;" :: "r"(sa), "l"(g));
}
__device__ __forceinline__ void mma_tf32(float* d, const uint32_t* a, const uint32_t* b) {
    asm volatile(
        "mma.sync.aligned.m16n8k8.row.col.f32.tf32.tf32.f32 "
        "{%0,%1,%2,%3}, {%4,%5,%6,%7}, {%8,%9}, {%0,%1,%2,%3};"
        : "+f"(d[0]), "+f"(d[1]), "+f"(d[2]), "+f"(d[3])
        : "r"(a[0]), "r"(a[1]), "r"(a[2]), "r"(a[3]), "r"(b[0]), "r"(b[1]));
}

// ======================= tf32 rounding pass =======================
__global__ void __launch_bounds__(256)
round_kernel(const float* __restrict__ src, float* __restrict__ dst)
{
    int i = blockIdx.x * 256 + threadIdx.x;
    float4 v = *(const float4*)(src + (size_t)i * 4);
    v.x = rnd_tf32(v.x); v.y = rnd_tf32(v.y); v.z = rnd_tf32(v.z); v.w = rnd_tf32(v.w);
    *(float4*)(dst + (size_t)i * 4) = v;
}

// ======================= tf32 mma.sync GEMM: C[M,N] = A[M,K] * B[N,K]^T =======================
// CTA tile 128x128, 8 warps (2 rows x 4 cols), warp tile 64x32, KB=16, 3-stage cp.async.
// MODE 0: A = g_hr, B = g_wq, C = g_qkv (NC=4096), epilogue = phi on q/k1/k2 groups
// MODE 1: A = g_lo, B = g_wo, C = g_x   (NC=1024), epilogue = + residual R (orig h)
#define KB 16
#define GITERS (DM / KB)     // 64
#define STG 3
#define ASTRIDE 20           // padded row stride (floats) -> conflict-free LDS
#define STAGE_FLOATS (128 * ASTRIDE)
#define GEMM_SMEM_BYTES (STG * 2 * STAGE_FLOATS * 4)   // 61440

template<int MODE>
__global__ void __launch_bounds__(256)
gemm_mma(const float* __restrict__ A, const float* __restrict__ Bm,
         const float* __restrict__ R, float* __restrict__ C, int NC)
{
    extern __shared__ float smem[];
    const int tid = threadIdx.x;
    const int wid = tid >> 5, lane = tid & 31;
    const int wR = wid >> 2, wC = wid & 3;
    const int qr = lane >> 2, qc = lane & 3;
    const int m0 = blockIdx.y * 128, n0 = blockIdx.x * 128;

    float acc[4][4][4];
#pragma unroll
    for (int mt = 0; mt < 4; mt++)
#pragma unroll
        for (int nt = 0; nt < 4; nt++)
#pragma unroll
            for (int c = 0; c < 4; c++) acc[mt][nt][c] = 0.f;

    const int lr = tid >> 2, lc4 = (tid & 3) * 4;

    // stage loader: A tile 128x16, B tile 128x16 (2 float4 each per thread)
    auto issue = [&](int it) {
        if (it < GITERS) {
            int s = it % STG;
            float* As = smem + s * 2 * STAGE_FLOATS;
            float* Bs = As + STAGE_FLOATS;
            int k0 = it * KB;
            cp16(&As[lr * ASTRIDE + lc4],        A  + (size_t)(m0 + lr) * DM + k0 + lc4);
            cp16(&As[(lr + 64) * ASTRIDE + lc4], A  + (size_t)(m0 + lr + 64) * DM + k0 + lc4);
            cp16(&Bs[lr * ASTRIDE + lc4],        Bm + (size_t)(n0 + lr) * DM + k0 + lc4);
            cp16(&Bs[(lr + 64) * ASTRIDE + lc4], Bm + (size_t)(n0 + lr + 64) * DM + k0 + lc4);
        }
        asm volatile("cp.async.commit_group;" ::: "memory");
    };

    issue(0);
    issue(1);

#pragma unroll 1
    for (int it = 0; it < GITERS; ++it) {
        asm volatile("cp.async.wait_group 1;" ::: "memory");
        __syncthreads();
        issue(it + 2);

        const int s = it % STG;
        const float* As = smem + s * 2 * STAGE_FLOATS;
        const float* Bs = As + STAGE_FLOATS;
        const uint32_t* Au = (const uint32_t*)As;
        const uint32_t* Bu = (const uint32_t*)Bs;

#pragma unroll
        for (int ks = 0; ks < 2; ks++) {
            uint32_t a[4][4], b[4][2];
            const int kb = ks * 8 + qc;
#pragma unroll
            for (int mt = 0; mt < 4; mt++) {
                const int r0 = wR * 64 + mt * 16 + qr;
                a[mt][0] = Au[r0 * ASTRIDE + kb];
                a[mt][1] = Au[(r0 + 8) * ASTRIDE + kb];
                a[mt][2] = Au[r0 * ASTRIDE + kb + 4];
                a[mt][3] = Au[(r0 + 8) * ASTRIDE + kb + 4];
            }
#pragma unroll
            for (int nt = 0; nt < 4; nt++) {
                const int c0 = wC * 32 + nt * 8 + qr;
                b[nt][0] = Bu[c0 * ASTRIDE + kb];
                b[nt][1] = Bu[c0 * ASTRIDE + kb + 4];
            }
#pragma unroll
            for (int mt = 0; mt < 4; mt++)
#pragma unroll
                for (int nt = 0; nt < 4; nt++)
                    mma_tf32(acc[mt][nt], a[mt], b[nt]);
        }
    }
    asm volatile("cp.async.wait_group 0;" ::: "memory");
    __syncthreads();

    if (MODE == 0) {
        const int which = (n0 >> 7) & 3;   // 0=q,1=k1,2=k2,3=v
        float inv[4][2];
#pragma unroll
        for (int mt = 0; mt < 4; mt++) { inv[mt][0] = 1.f; inv[mt][1] = 1.f; }
        if (which < 3) {
            // transform: elu(x)+1
#pragma unroll
            for (int mt = 0; mt < 4; mt++)
#pragma unroll
                for (int nt = 0; nt < 4; nt++)
#pragma unroll
                    for (int c = 0; c < 4; c++) {
                        float x = acc[mt][nt][c];
                        acc[mt][nt][c] = (x > 0.f) ? x + 1.f : __expf(x);
                    }
            // row sums: quad shfl then cross-warpCol smem reduction
#pragma unroll
            for (int mt = 0; mt < 4; mt++)
#pragma unroll
                for (int hh = 0; hh < 2; hh++) {
                    float v = 0.f;
#pragma unroll
                    for (int nt = 0; nt < 4; nt++)
                        v += acc[mt][nt][hh * 2] + acc[mt][nt][hh * 2 + 1];
                    v += __shfl_xor_sync(0xffffffffu, v, 1);
                    v += __shfl_xor_sync(0xffffffffu, v, 2);
                    if (qc == 0)
                        smem[(wR * 64 + mt * 16 + hh * 8 + qr) * 4 + wC] = v;
                }
            __syncthreads();
#pragma unroll
            for (int mt = 0; mt < 4; mt++)
#pragma unroll
                for (int hh = 0; hh < 2; hh++) {
                    int row = wR * 64 + mt * 16 + hh * 8 + qr;
                    float s = smem[row * 4 + 0] + smem[row * 4 + 1] +
                              smem[row * 4 + 2] + smem[row * 4 + 3];
                    inv[mt][hh] = 1.f / s;
                }
        }
        // store (values already tf32-exact inputs to attention? phi output is fp32; attention is fp32 SIMT -> fine)
#pragma unroll
        for (int mt = 0; mt < 4; mt++)
#pragma unroll
            for (int hh = 0; hh < 2; hh++) {
                const int row = m0 + wR * 64 + mt * 16 + hh * 8 + qr;
                const float iv = inv[mt][hh];
#pragma unroll
                for (int nt = 0; nt < 4; nt++) {
                    float2 o;
                    o.x = acc[mt][nt][hh * 2]     * iv;
                    o.y = acc[mt][nt][hh * 2 + 1] * iv;
                    *(float2*)(C + (size_t)row * NC + n0 + wC * 32 + nt * 8 + qc * 2) = o;
                }
            }
    } else {
        // residual add + store
#pragma unroll
        for (int mt = 0; mt < 4; mt++)
#pragma unroll
            for (int hh = 0; hh < 2; hh++) {
                const int row = m0 + wR * 64 + mt * 16 + hh * 8 + qr;
#pragma unroll
                for (int nt = 0; nt < 4; nt++) {
                    const int col = n0 + wC * 32 + nt * 8 + qc * 2;
                    float2 rr = *(const float2*)(R + (size_t)row * DM + col);
                    float2 o;
                    o.x = acc[mt][nt][hh * 2]     + rr.x;
                    o.y = acc[mt][nt][hh * 2 + 1] + rr.y;
                    *(float2*)(C + (size_t)row * NC + col) = o;
                }
            }
    }
}

// ======================= fused dual causal linear attention (SIMT fp32) =======================
#define ATTN_SMEM_FLOATS (3*128*68 + 64*132 + 64*68)
#define ATTN_SMEM_BYTES (ATTN_SMEM_FLOATS * 4)

__global__ void __launch_bounds__(256)
attn_kernel(const float* __restrict__ pi0)
{
    extern __shared__ float sm[];
    float* Qs  = sm;                    // [128 d][68]
    float* K1s = Qs  + 128*68;
    float* K2s = K1s + 128*68;
    float* Vs  = K2s + 128*68;          // [64 s][132]
    float* Ps  = Vs  + 64*132;          // [64 s][68]

    const int tid = threadIdx.x;
    const int ty = tid >> 4, tx = tid & 15;
    const int tt = blockIdx.x;
    const int bh = blockIdx.y;
    const int b  = bh >> 3, head = bh & 7;
    const int t0 = tt * 64;

#pragma unroll
    for (int p = 0; p < 8; p++) {
        int idx = tid + p * 256;
        int row = idx >> 5, d = (idx & 31) << 2;
        float4 q = *(const float4*)&g_qkv[((size_t)(t0 + row) * BSZ + b) * NQ + head * 512 + d];
        Qs[(d+0)*68 + row] = q.x; Qs[(d+1)*68 + row] = q.y;
        Qs[(d+2)*68 + row] = q.z; Qs[(d+3)*68 + row] = q.w;
    }

    float pclip[4];
#pragma unroll
    for (int i = 0; i < 4; i++) {
        float p = pi0[head * 256 + t0 + ty*4 + i];
        pclip[i] = fminf(fmaxf(p, 0.f), 1.f);
    }

    float acc[4][8];
#pragma unroll
    for (int i = 0; i < 4; i++)
#pragma unroll
        for (int j = 0; j < 8; j++) acc[i][j] = 0.f;

    for (int st = 0; st <= tt; st++) {
        const int s0 = st * 64;
        if (st > 0) __syncthreads();
#pragma unroll
        for (int p = 0; p < 8; p++) {
            int idx = tid + p * 256;
            int row = idx >> 5, d = (idx & 31) << 2;
            size_t base = ((size_t)(s0 + row) * BSZ + b) * NQ + head * 512;
            float4 k1 = *(const float4*)&g_qkv[base + 128 + d];
            float4 k2 = *(const float4*)&g_qkv[base + 256 + d];
            float4 vv = *(const float4*)&g_qkv[base + 384 + d];
            K1s[(d+0)*68+row]=k1.x; K1s[(d+1)*68+row]=k1.y; K1s[(d+2)*68+row]=k1.z; K1s[(d+3)*68+row]=k1.w;
            K2s[(d+0)*68+row]=k2.x; K2s[(d+1)*68+row]=k2.y; K2s[(d+2)*68+row]=k2.z; K2s[(d+3)*68+row]=k2.w;
            *(float4*)&Vs[row*132 + d] = vv;
        }
        __syncthreads();

        float p1[4][4], p2[4][4];
#pragma unroll
        for (int i = 0; i < 4; i++)
#pragma unroll
            for (int j = 0; j < 4; j++) { p1[i][j] = 0.f; p2[i][j] = 0.f; }

#pragma unroll 4
        for (int d = 0; d < 128; d++) {
            float4 qa = *(const float4*)&Qs[d*68 + ty*4];
            float4 ka = *(const float4*)&K1s[d*68 + tx*4];
            float4 kb = *(const float4*)&K2s[d*68 + tx*4];
            float qv[4]  = {qa.x, qa.y, qa.z, qa.w};
            float k1v[4] = {ka.x, ka.y, ka.z, ka.w};
            float k2v[4] = {kb.x, kb.y, kb.z, kb.w};
#pragma unroll
            for (int i = 0; i < 4; i++)
#pragma unroll
                for (int j = 0; j < 4; j++) {
                    p1[i][j] = fmaf(qv[i], k1v[j], p1[i][j]);
                    p2[i][j] = fmaf(qv[i], k2v[j], p2[i][j]);
                }
        }

        const bool diag = (st == tt);
#pragma unroll
        for (int i = 0; i < 4; i++)
#pragma unroll
            for (int j = 0; j < 4; j++) {
                float v = pclip[i]*p1[i][j] + (1.f - pclip[i])*p2[i][j];
                if (diag && (tx*4 + j) > (ty*4 + i)) v = 0.f;
                Ps[(tx*4 + j)*68 + (ty*4 + i)] = v;
            }
        __syncthreads();

#pragma unroll 8
        for (int s = 0; s < 64; s++) {
            float4 pa = *(const float4*)&Ps[s*68 + ty*4];
            float4 v0 = *(const float4*)&Vs[s*132 + tx*8];
            float4 v1 = *(const float4*)&Vs[s*132 + tx*8 + 4];
            float pv[4] = {pa.x, pa.y, pa.z, pa.w};
            float vv[8] = {v0.x, v0.y, v0.z, v0.w, v1.x, v1.y, v1.z, v1.w};
#pragma unroll
            for (int i = 0; i < 4; i++)
#pragma unroll
                for (int j = 0; j < 8; j++) acc[i][j] = fmaf(pv[i], vv[j], acc[i][j]);
        }
    }

    // store layer_out, rounded to tf32 (it feeds the MODE 1 mma GEMM as A operand)
#pragma unroll
    for (int i = 0; i < 4; i++) {
        int t = t0 + ty*4 + i;
        float* dst = &g_lo[((size_t)t * BSZ + b) * DM + head*DH + tx*8];
        float4 o;
        o.x = rnd_tf32(SCALE_F*acc[i][0]); o.y = rnd_tf32(SCALE_F*acc[i][1]);
        o.z = rnd_tf32(SCALE_F*acc[i][2]); o.w = rnd_tf32(SCALE_F*acc[i][3]);
        *(float4*)dst = o;
        o.x = rnd_tf32(SCALE_F*acc[i][4]); o.y = rnd_tf32(SCALE_F*acc[i][5]);
        o.z = rnd_tf32(SCALE_F*acc[i][6]); o.w = rnd_tf32(SCALE_F*acc[i][7]);
        *(float4*)(dst + 4) = o;
    }
}

// ======================= LayerNorm =======================
__global__ void __launch_bounds__(256)
ln_kernel(const float* __restrict__ gamma, const float* __restrict__ beta,
          float* __restrict__ out)
{
    __shared__ float red[8];
    const int r = blockIdx.x, tid = threadIdx.x;
    const int lane = tid & 31, wid = tid >> 5;
    float4 v = *(const float4*)&g_x[(size_t)r * DM + tid * 4];
    float s = v.x + v.y + v.z + v.w;
#pragma unroll
    for (int o = 16; o > 0; o >>= 1) s += __shfl_xor_sync(0xffffffffu, s, o);
    if (lane == 0) red[wid] = s;
    __syncthreads();
    float tot = 0.f;
#pragma unroll
    for (int i = 0; i < 8; i++) tot += red[i];
    float mu = tot * (1.f / DM);
    float d0 = v.x - mu, d1 = v.y - mu, d2 = v.z - mu, d3 = v.w - mu;
    float sq = d0*d0 + d1*d1 + d2*d2 + d3*d3;
#pragma unroll
    for (int o = 16; o > 0; o >>= 1) sq += __shfl_xor_sync(0xffffffffu, sq, o);
    __syncthreads();
    if (lane == 0) red[wid] = sq;
    __syncthreads();
    float tot2 = 0.f;
#pragma unroll
    for (int i = 0; i < 8; i++) tot2 += red[i];
    float inv = rsqrtf(tot2 * (1.f / DM) + LN_EPS_F);
    float4 g = *(const float4*)&gamma[tid * 4];
    float4 bt = *(const float4*)&beta[tid * 4];
    float4 o;
    o.x = g.x * d0 * inv + bt.x;
    o.y = g.y * d1 * inv + bt.y;
    o.z = g.z * d2 * inv + bt.z;
    o.w = g.w * d3 * inv + bt.w;
    *(float4*)&out[(size_t)r * DM + tid * 4] = o;
}

// ======================= launch =======================
extern "C" void kernel_launch(void* const* d_in, const int* in_sizes, int n_in,
                              void* d_out, int out_size)
{
    const float* h     = (const float*)d_in[0];
    const float* Wqkv  = (const float*)d_in[1];
    const float* Wo    = (const float*)d_in[2];
    const float* pi0   = (const float*)d_in[3];
    const float* gamma = (const float*)d_in[4];
    const float* beta  = (const float*)d_in[5];
    float* out = (float*)d_out;

    float *p_hr, *p_wq, *p_wo, *p_qkv, *p_lo, *p_x;
    cudaGetSymbolAddress((void**)&p_hr, g_hr);
    cudaGetSymbolAddress((void**)&p_wq, g_wq);
    cudaGetSymbolAddress((void**)&p_wo, g_wo);
    cudaGetSymbolAddress((void**)&p_qkv, g_qkv);
    cudaGetSymbolAddress((void**)&p_lo, g_lo);
    cudaGetSymbolAddress((void**)&p_x, g_x);

    cudaFuncSetAttribute(gemm_mma<0>, cudaFuncAttributeMaxDynamicSharedMemorySize, GEMM_SMEM_BYTES);
    cudaFuncSetAttribute(gemm_mma<1>, cudaFuncAttributeMaxDynamicSharedMemorySize, GEMM_SMEM_BYTES);
    cudaFuncSetAttribute(attn_kernel, cudaFuncAttributeMaxDynamicSharedMemorySize, ATTN_SMEM_BYTES);

    // 0. round inputs to tf32
    round_kernel<<<(MROWS * DM) / 1024, 256>>>(h, p_hr);
    round_kernel<<<(NQ * DM) / 1024, 256>>>(Wqkv, p_wq);
    round_kernel<<<(DM * DM) / 1024, 256>>>(Wo, p_wo);

    // 1. qkv = h @ Wqkv^T (tf32 mma.sync), phi fused
    gemm_mma<0><<<dim3(NQ / 128, MROWS / 128), 256, GEMM_SMEM_BYTES>>>(p_hr, p_wq, nullptr, p_qkv, NQ);

    // 2. fused dual causal linear attention -> g_lo (tf32-rounded)
    attn_kernel<<<dim3(LSEQ/64, BSZ*NH), 256, ATTN_SMEM_BYTES>>>(pi0);

    // 3. x = g_lo @ Wo^T + h (residual fused)
    gemm_mma<1><<<dim3(DM / 128, MROWS / 128), 256, GEMM_SMEM_BYTES>>>(p_lo, p_wo, h, p_x, DM);

    // 4. LayerNorm -> out
    ln_kernel<<<MROWS, 256>>>(gamma, beta, out);
}

// round 5
// speedup vs baseline: 3.5500x; 1.7986x over previous
#include <cuda_runtime.h>
#include <cuda_bf16.h>
#include <cstdint>
#include <math.h>

#define LSEQ 256
#define BSZ  64
#define NH   8
#define DH   128
#define DM   1024
#define NQ   4096
#define MROWS (LSEQ*BSZ)
#define SCALE_F 0.08838834764831845f
#define LN_EPS_F 1e-5f

// ---- scratch (static device arrays; no allocation) ----
__device__ float g_qkv[(size_t)MROWS * NQ];          // phi(q,k1,k2), v   fp32
__device__ float g_x  [(size_t)MROWS * DM];          // h + attn_out      fp32
__device__ __nv_bfloat16 g_hb [(size_t)MROWS * DM];  // h  in bf16
__device__ __nv_bfloat16 g_wqb[(size_t)NQ * DM];     // Wqkv in bf16
__device__ __nv_bfloat16 g_wob[(size_t)DM * DM];     // Wo in bf16
__device__ __nv_bfloat16 g_lob[(size_t)MROWS * DM];  // layer_out in bf16

// ======================= helpers =======================
__device__ __forceinline__ uint32_t smem_u32(const void* p) {
    uint32_t a;
    asm("{ .reg .u64 t; cvta.to.shared.u64 t, %1; cvt.u32.u64 %0, t; }" : "=r"(a) : "l"(p));
    return a;
}
__device__ __forceinline__ void cp16(void* s, const void* g) {
    uint32_t sa = smem_u32(s);
    asm volatile("cp.async.cg.shared.global [%0], [%1], 16;" :: "r"(sa), "l"(g));
}
#define LDSM4(r0, r1, r2, r3, addr) \
    asm volatile("ldmatrix.sync.aligned.m8n8.x4.shared.b16 {%0,%1,%2,%3}, [%4];" \
                 : "=r"(r0), "=r"(r1), "=r"(r2), "=r"(r3) : "r"(addr))
__device__ __forceinline__ void mma_bf16(float* d, const uint32_t* a,
                                         uint32_t b0, uint32_t b1) {
    asm volatile(
        "mma.sync.aligned.m16n8k16.row.col.f32.bf16.bf16.f32 "
        "{%0,%1,%2,%3}, {%4,%5,%6,%7}, {%8,%9}, {%0,%1,%2,%3};"
        : "+f"(d[0]), "+f"(d[1]), "+f"(d[2]), "+f"(d[3])
        : "r"(a[0]), "r"(a[1]), "r"(a[2]), "r"(a[3]), "r"(b0), "r"(b1));
}

// ======================= fp32 -> bf16 conversion pass =======================
__global__ void __launch_bounds__(256)
cvt_bf16(const float* __restrict__ src, __nv_bfloat16* __restrict__ dst)
{
    size_t i = ((size_t)blockIdx.x * 256 + threadIdx.x) * 4;
    float4 v = *(const float4*)(src + i);
    __nv_bfloat162 a = __floats2bfloat162_rn(v.x, v.y);
    __nv_bfloat162 b = __floats2bfloat162_rn(v.z, v.w);
    uint2 o;
    o.x = *(uint32_t*)&a;
    o.y = *(uint32_t*)&b;
    *(uint2*)(dst + i) = o;
}

// ======================= bf16 mma.sync GEMM: C[M,N] = A[M,K] * B[N,K]^T =======================
// CTA 128x128, 8 warps (2x4), warp 64x32, KB=32 halves per stage, 3-stage cp.async,
// ldmatrix.x4 fragment loads, 80B padded row stride (conflict-free LDSM).
// MODE 0: C = g_qkv (NC=4096), epilogue = phi on q/k1/k2 groups
// MODE 1: C = g_x   (NC=1024), epilogue = + residual R (orig h fp32)
#define KB 32
#define GITERS (DM / KB)            // 32
#define STG 3
#define RSH 40                      // row stride in halves (80 bytes)
#define STAGE_HALVES (128 * RSH)    // 5120 halves = 10240 B
#define GEMM_SMEM_BYTES (STG * 2 * STAGE_HALVES * 2)   // 61440

template<int MODE>
__global__ void __launch_bounds__(256, 2)
gemm_mma(const __nv_bfloat16* __restrict__ A, const __nv_bfloat16* __restrict__ Bm,
         const float* __restrict__ R, float* __restrict__ C, int NC)
{
    extern __shared__ __align__(16) char smraw[];
    __nv_bfloat16* smh = (__nv_bfloat16*)smraw;
    float* smf = (float*)smraw;
    const int tid = threadIdx.x;
    const int wid = tid >> 5, lane = tid & 31;
    const int wR = wid >> 2, wC = wid & 3;
    const int qr = lane >> 2, qc = lane & 3;
    const int m0 = blockIdx.y * 128, n0 = blockIdx.x * 128;

    float acc[4][4][4];
#pragma unroll
    for (int mt = 0; mt < 4; mt++)
#pragma unroll
        for (int nt = 0; nt < 4; nt++)
#pragma unroll
            for (int c = 0; c < 4; c++) acc[mt][nt][c] = 0.f;

    const int lrow = tid >> 2, lc = (tid & 3) * 8;   // 4 chunks of 8 halves per 64B row

    auto issue = [&](int it) {
        if (it < GITERS) {
            const int s = it % STG;
            __nv_bfloat16* As = smh + s * 2 * STAGE_HALVES;
            __nv_bfloat16* Bs = As + STAGE_HALVES;
            const int k0 = it * KB;
            cp16(&As[lrow * RSH + lc],        A  + (size_t)(m0 + lrow) * DM + k0 + lc);
            cp16(&As[(lrow + 64) * RSH + lc], A  + (size_t)(m0 + lrow + 64) * DM + k0 + lc);
            cp16(&Bs[lrow * RSH + lc],        Bm + (size_t)(n0 + lrow) * DM + k0 + lc);
            cp16(&Bs[(lrow + 64) * RSH + lc], Bm + (size_t)(n0 + lrow + 64) * DM + k0 + lc);
        }
        asm volatile("cp.async.commit_group;" ::: "memory");
    };

    issue(0);
    issue(1);

    // per-thread ldmatrix base offsets (bytes)
    const uint32_t a_lane_off = ((wR * 64 + (lane & 15)) * RSH + ((lane >> 4) << 3)) * 2;
    const uint32_t b_lane_off = ((wC * 32 + ((lane >> 4) << 3) + (lane & 7)) * RSH +
                                 (((lane >> 3) & 1) << 3)) * 2;

#pragma unroll 1
    for (int it = 0; it < GITERS; ++it) {
        asm volatile("cp.async.wait_group 1;" ::: "memory");
        __syncthreads();
        issue(it + 2);

        const int s = it % STG;
        const uint32_t abase = smem_u32(smh + s * 2 * STAGE_HALVES) + a_lane_off;
        const uint32_t bbase = smem_u32(smh + s * 2 * STAGE_HALVES + STAGE_HALVES) + b_lane_off;

#pragma unroll
        for (int ks = 0; ks < 2; ks++) {
            uint32_t a[4][4], b[2][4];
#pragma unroll
            for (int mt = 0; mt < 4; mt++)
                LDSM4(a[mt][0], a[mt][1], a[mt][2], a[mt][3],
                      abase + mt * (16 * RSH * 2) + ks * 32);
#pragma unroll
            for (int nt2 = 0; nt2 < 2; nt2++)
                LDSM4(b[nt2][0], b[nt2][1], b[nt2][2], b[nt2][3],
                      bbase + nt2 * (16 * RSH * 2) + ks * 32);
#pragma unroll
            for (int mt = 0; mt < 4; mt++) {
                mma_bf16(acc[mt][0], a[mt], b[0][0], b[0][1]);
                mma_bf16(acc[mt][1], a[mt], b[0][2], b[0][3]);
                mma_bf16(acc[mt][2], a[mt], b[1][0], b[1][1]);
                mma_bf16(acc[mt][3], a[mt], b[1][2], b[1][3]);
            }
        }
    }
    asm volatile("cp.async.wait_group 0;" ::: "memory");
    __syncthreads();

    if (MODE == 0) {
        const int which = (n0 >> 7) & 3;   // 0=q,1=k1,2=k2,3=v
        float inv[4][2];
#pragma unroll
        for (int mt = 0; mt < 4; mt++) { inv[mt][0] = 1.f; inv[mt][1] = 1.f; }
        if (which < 3) {
#pragma unroll
            for (int mt = 0; mt < 4; mt++)
#pragma unroll
                for (int nt = 0; nt < 4; nt++)
#pragma unroll
                    for (int c = 0; c < 4; c++) {
                        float x = acc[mt][nt][c];
                        acc[mt][nt][c] = (x > 0.f) ? x + 1.f : __expf(x);
                    }
#pragma unroll
            for (int mt = 0; mt < 4; mt++)
#pragma unroll
                for (int hh = 0; hh < 2; hh++) {
                    float v = 0.f;
#pragma unroll
                    for (int nt = 0; nt < 4; nt++)
                        v += acc[mt][nt][hh * 2] + acc[mt][nt][hh * 2 + 1];
                    v += __shfl_xor_sync(0xffffffffu, v, 1);
                    v += __shfl_xor_sync(0xffffffffu, v, 2);
                    if (qc == 0)
                        smf[(wR * 64 + mt * 16 + hh * 8 + qr) * 4 + wC] = v;
                }
            __syncthreads();
#pragma unroll
            for (int mt = 0; mt < 4; mt++)
#pragma unroll
                for (int hh = 0; hh < 2; hh++) {
                    int row = wR * 64 + mt * 16 + hh * 8 + qr;
                    float s = smf[row * 4 + 0] + smf[row * 4 + 1] +
                              smf[row * 4 + 2] + smf[row * 4 + 3];
                    inv[mt][hh] = 1.f / s;
                }
        }
#pragma unroll
        for (int mt = 0; mt < 4; mt++)
#pragma unroll
            for (int hh = 0; hh < 2; hh++) {
                const int row = m0 + wR * 64 + mt * 16 + hh * 8 + qr;
                const float iv = inv[mt][hh];
#pragma unroll
                for (int nt = 0; nt < 4; nt++) {
                    float2 o;
                    o.x = acc[mt][nt][hh * 2]     * iv;
                    o.y = acc[mt][nt][hh * 2 + 1] * iv;
                    *(float2*)(C + (size_t)row * NC + n0 + wC * 32 + nt * 8 + qc * 2) = o;
                }
            }
    } else {
#pragma unroll
        for (int mt = 0; mt < 4; mt++)
#pragma unroll
            for (int hh = 0; hh < 2; hh++) {
                const int row = m0 + wR * 64 + mt * 16 + hh * 8 + qr;
#pragma unroll
                for (int nt = 0; nt < 4; nt++) {
                    const int col = n0 + wC * 32 + nt * 8 + qc * 2;
                    float2 rr = *(const float2*)(R + (size_t)row * DM + col);
                    float2 o;
                    o.x = acc[mt][nt][hh * 2]     + rr.x;
                    o.y = acc[mt][nt][hh * 2 + 1] + rr.y;
                    *(float2*)(C + (size_t)row * NC + col) = o;
                }
            }
    }
}

// ======================= fused dual causal linear attention (SIMT fp32) =======================
#define ATTN_SMEM_FLOATS (3*128*68 + 64*132 + 64*68)
#define ATTN_SMEM_BYTES (ATTN_SMEM_FLOATS * 4)

__global__ void __launch_bounds__(256)
attn_kernel(const float* __restrict__ pi0)
{
    extern __shared__ float sm[];
    float* Qs  = sm;                    // [128 d][68]
    float* K1s = Qs  + 128*68;
    float* K2s = K1s + 128*68;
    float* Vs  = K2s + 128*68;          // [64 s][132]
    float* Ps  = Vs  + 64*132;          // [64 s][68]

    const int tid = threadIdx.x;
    const int ty = tid >> 4, tx = tid & 15;
    const int tt = blockIdx.x;
    const int bh = blockIdx.y;
    const int b  = bh >> 3, head = bh & 7;
    const int t0 = tt * 64;

#pragma unroll
    for (int p = 0; p < 8; p++) {
        int idx = tid + p * 256;
        int row = idx >> 5, d = (idx & 31) << 2;
        float4 q = *(const float4*)&g_qkv[((size_t)(t0 + row) * BSZ + b) * NQ + head * 512 + d];
        Qs[(d+0)*68 + row] = q.x; Qs[(d+1)*68 + row] = q.y;
        Qs[(d+2)*68 + row] = q.z; Qs[(d+3)*68 + row] = q.w;
    }

    float pclip[4];
#pragma unroll
    for (int i = 0; i < 4; i++) {
        float p = pi0[head * 256 + t0 + ty*4 + i];
        pclip[i] = fminf(fmaxf(p, 0.f), 1.f);
    }

    float acc[4][8];
#pragma unroll
    for (int i = 0; i < 4; i++)
#pragma unroll
        for (int j = 0; j < 8; j++) acc[i][j] = 0.f;

    for (int st = 0; st <= tt; st++) {
        const int s0 = st * 64;
        if (st > 0) __syncthreads();
#pragma unroll
        for (int p = 0; p < 8; p++) {
            int idx = tid + p * 256;
            int row = idx >> 5, d = (idx & 31) << 2;
            size_t base = ((size_t)(s0 + row) * BSZ + b) * NQ + head * 512;
            float4 k1 = *(const float4*)&g_qkv[base + 128 + d];
            float4 k2 = *(const float4*)&g_qkv[base + 256 + d];
            float4 vv = *(const float4*)&g_qkv[base + 384 + d];
            K1s[(d+0)*68+row]=k1.x; K1s[(d+1)*68+row]=k1.y; K1s[(d+2)*68+row]=k1.z; K1s[(d+3)*68+row]=k1.w;
            K2s[(d+0)*68+row]=k2.x; K2s[(d+1)*68+row]=k2.y; K2s[(d+2)*68+row]=k2.z; K2s[(d+3)*68+row]=k2.w;
            *(float4*)&Vs[row*132 + d] = vv;
        }
        __syncthreads();

        float p1[4][4], p2[4][4];
#pragma unroll
        for (int i = 0; i < 4; i++)
#pragma unroll
            for (int j = 0; j < 4; j++) { p1[i][j] = 0.f; p2[i][j] = 0.f; }

#pragma unroll 4
        for (int d = 0; d < 128; d++) {
            float4 qa = *(const float4*)&Qs[d*68 + ty*4];
            float4 ka = *(const float4*)&K1s[d*68 + tx*4];
            float4 kb = *(const float4*)&K2s[d*68 + tx*4];
            float qv[4]  = {qa.x, qa.y, qa.z, qa.w};
            float k1v[4] = {ka.x, ka.y, ka.z, ka.w};
            float k2v[4] = {kb.x, kb.y, kb.z, kb.w};
#pragma unroll
            for (int i = 0; i < 4; i++)
#pragma unroll
                for (int j = 0; j < 4; j++) {
                    p1[i][j] = fmaf(qv[i], k1v[j], p1[i][j]);
                    p2[i][j] = fmaf(qv[i], k2v[j], p2[i][j]);
                }
        }

        const bool diag = (st == tt);
#pragma unroll
        for (int i = 0; i < 4; i++)
#pragma unroll
            for (int j = 0; j < 4; j++) {
                float v = pclip[i]*p1[i][j] + (1.f - pclip[i])*p2[i][j];
                if (diag && (tx*4 + j) > (ty*4 + i)) v = 0.f;
                Ps[(tx*4 + j)*68 + (ty*4 + i)] = v;
            }
        __syncthreads();

#pragma unroll 8
        for (int s = 0; s < 64; s++) {
            float4 pa = *(const float4*)&Ps[s*68 + ty*4];
            float4 v0 = *(const float4*)&Vs[s*132 + tx*8];
            float4 v1 = *(const float4*)&Vs[s*132 + tx*8 + 4];
            float pv[4] = {pa.x, pa.y, pa.z, pa.w};
            float vv[8] = {v0.x, v0.y, v0.z, v0.w, v1.x, v1.y, v1.z, v1.w};
#pragma unroll
            for (int i = 0; i < 4; i++)
#pragma unroll
                for (int j = 0; j < 8; j++) acc[i][j] = fmaf(pv[i], vv[j], acc[i][j]);
        }
    }

    // store layer_out as bf16 (feeds MODE 1 GEMM A operand)
#pragma unroll
    for (int i = 0; i < 4; i++) {
        int t = t0 + ty*4 + i;
        __nv_bfloat16* dst = &g_lob[((size_t)t * BSZ + b) * DM + head*DH + tx*8];
        __nv_bfloat162 p0 = __floats2bfloat162_rn(SCALE_F*acc[i][0], SCALE_F*acc[i][1]);
        __nv_bfloat162 p1b = __floats2bfloat162_rn(SCALE_F*acc[i][2], SCALE_F*acc[i][3]);
        __nv_bfloat162 p2b = __floats2bfloat162_rn(SCALE_F*acc[i][4], SCALE_F*acc[i][5]);
        __nv_bfloat162 p3 = __floats2bfloat162_rn(SCALE_F*acc[i][6], SCALE_F*acc[i][7]);
        uint4 o;
        o.x = *(uint32_t*)&p0; o.y = *(uint32_t*)&p1b;
        o.z = *(uint32_t*)&p2b; o.w = *(uint32_t*)&p3;
        *(uint4*)dst = o;
    }
}

// ======================= LayerNorm =======================
__global__ void __launch_bounds__(256)
ln_kernel(const float* __restrict__ gamma, const float* __restrict__ beta,
          float* __restrict__ out)
{
    __shared__ float red[8];
    const int r = blockIdx.x, tid = threadIdx.x;
    const int lane = tid & 31, wid = tid >> 5;
    float4 v = *(const float4*)&g_x[(size_t)r * DM + tid * 4];
    float s = v.x + v.y + v.z + v.w;
#pragma unroll
    for (int o = 16; o > 0; o >>= 1) s += __shfl_xor_sync(0xffffffffu, s, o);
    if (lane == 0) red[wid] = s;
    __syncthreads();
    float tot = 0.f;
#pragma unroll
    for (int i = 0; i < 8; i++) tot += red[i];
    float mu = tot * (1.f / DM);
    float d0 = v.x - mu, d1 = v.y - mu, d2 = v.z - mu, d3 = v.w - mu;
    float sq = d0*d0 + d1*d1 + d2*d2 + d3*d3;
#pragma unroll
    for (int o = 16; o > 0; o >>= 1) sq += __shfl_xor_sync(0xffffffffu, sq, o);
    __syncthreads();
    if (lane == 0) red[wid] = sq;
    __syncthreads();
    float tot2 = 0.f;
#pragma unroll
    for (int i = 0; i < 8; i++) tot2 += red[i];
    float inv = rsqrtf(tot2 * (1.f / DM) + LN_EPS_F);
    float4 g = *(const float4*)&gamma[tid * 4];
    float4 bt = *(const float4*)&beta[tid * 4];
    float4 o;
    o.x = g.x * d0 * inv + bt.x;
    o.y = g.y * d1 * inv + bt.y;
    o.z = g.z * d2 * inv + bt.z;
    o.w = g.w * d3 * inv + bt.w;
    *(float4*)&out[(size_t)r * DM + tid * 4] = o;
}

// ======================= launch =======================
extern "C" void kernel_launch(void* const* d_in, const int* in_sizes, int n_in,
                              void* d_out, int out_size)
{
    const float* h     = (const float*)d_in[0];
    const float* Wqkv  = (const float*)d_in[1];
    const float* Wo    = (const float*)d_in[2];
    const float* pi0   = (const float*)d_in[3];
    const float* gamma = (const float*)d_in[4];
    const float* beta  = (const float*)d_in[5];
    float* out = (float*)d_out;

    float *p_qkv, *p_x;
    __nv_bfloat16 *p_hb, *p_wqb, *p_wob, *p_lob;
    cudaGetSymbolAddress((void**)&p_qkv, g_qkv);
    cudaGetSymbolAddress((void**)&p_x, g_x);
    cudaGetSymbolAddress((void**)&p_hb, g_hb);
    cudaGetSymbolAddress((void**)&p_wqb, g_wqb);
    cudaGetSymbolAddress((void**)&p_wob, g_wob);
    cudaGetSymbolAddress((void**)&p_lob, g_lob);

    cudaFuncSetAttribute(gemm_mma<0>, cudaFuncAttributeMaxDynamicSharedMemorySize, GEMM_SMEM_BYTES);
    cudaFuncSetAttribute(gemm_mma<1>, cudaFuncAttributeMaxDynamicSharedMemorySize, GEMM_SMEM_BYTES);
    cudaFuncSetAttribute(attn_kernel, cudaFuncAttributeMaxDynamicSharedMemorySize, ATTN_SMEM_BYTES);

    // 0. convert inputs to bf16
    cvt_bf16<<<(MROWS * DM) / 1024, 256>>>(h, p_hb);
    cvt_bf16<<<(NQ * DM) / 1024, 256>>>(Wqkv, p_wqb);
    cvt_bf16<<<(DM * DM) / 1024, 256>>>(Wo, p_wob);

    // 1. qkv = h @ Wqkv^T (bf16 mma.sync), phi fused
    gemm_mma<0><<<dim3(NQ / 128, MROWS / 128), 256, GEMM_SMEM_BYTES>>>(p_hb, p_wqb, nullptr, p_qkv, NQ);

    // 2. fused dual causal linear attention -> g_lob (bf16)
    attn_kernel<<<dim3(LSEQ/64, BSZ*NH), 256, ATTN_SMEM_BYTES>>>(pi0);

    // 3. x = layer_out @ Wo^T + h (residual fused)
    gemm_mma<1><<<dim3(DM / 128, MROWS / 128), 256, GEMM_SMEM_BYTES>>>(p_lob, p_wob, h, p_x, DM);

    // 4. LayerNorm -> out
    ln_kernel<<<MROWS, 256>>>(gamma, beta, out);
}

// round 7
// speedup vs baseline: 6.1755x; 1.7396x over previous
#include <cuda_runtime.h>
#include <cuda_bf16.h>
#include <cstdint>
#include <math.h>

#define LSEQ 256
#define BSZ  64
#define NH   8
#define DH   128
#define DM   1024
#define NQ   4096
#define MROWS (LSEQ*BSZ)
#define SCALE_F 0.08838834764831845f
#define LN_EPS_F 1e-5f

// ---- scratch (static device arrays; no allocation) ----
__device__ float g_x  [(size_t)MROWS * DM];           // h + attn_out fp32
__device__ __nv_bfloat16 g_qkvb[(size_t)MROWS * NQ];  // phi(q,k1,k2), v  bf16
__device__ __nv_bfloat16 g_hb [(size_t)MROWS * DM];   // h bf16
__device__ __nv_bfloat16 g_wqb[(size_t)NQ * DM];      // Wqkv bf16
__device__ __nv_bfloat16 g_wob[(size_t)DM * DM];      // Wo bf16
__device__ __nv_bfloat16 g_lob[(size_t)MROWS * DM];   // layer_out bf16

// ======================= helpers =======================
__device__ __forceinline__ uint32_t smem_u32(const void* p) {
    uint32_t a;
    asm("{ .reg .u64 t; cvta.to.shared.u64 t, %1; cvt.u32.u64 %0, t; }" : "=r"(a) : "l"(p));
    return a;
}
__device__ __forceinline__ void cp16(void* s, const void* g) {
    uint32_t sa = smem_u32(s);
    asm volatile("cp.async.cg.shared.global [%0], [%1], 16;" :: "r"(sa), "l"(g));
}
#define LDSM4(r0, r1, r2, r3, addr) \
    asm volatile("ldmatrix.sync.aligned.m8n8.x4.shared.b16 {%0,%1,%2,%3}, [%4];" \
                 : "=r"(r0), "=r"(r1), "=r"(r2), "=r"(r3) : "r"(addr))
#define LDSM4T(r0, r1, r2, r3, addr) \
    asm volatile("ldmatrix.sync.aligned.m8n8.x4.trans.shared.b16 {%0,%1,%2,%3}, [%4];" \
                 : "=r"(r0), "=r"(r1), "=r"(r2), "=r"(r3) : "r"(addr))
__device__ __forceinline__ void mma_bf16(float* d, const uint32_t* a,
                                         uint32_t b0, uint32_t b1) {
    asm volatile(
        "mma.sync.aligned.m16n8k16.row.col.f32.bf16.bf16.f32 "
        "{%0,%1,%2,%3}, {%4,%5,%6,%7}, {%8,%9}, {%0,%1,%2,%3};"
        : "+f"(d[0]), "+f"(d[1]), "+f"(d[2]), "+f"(d[3])
        : "r"(a[0]), "r"(a[1]), "r"(a[2]), "r"(a[3]), "r"(b0), "r"(b1));
}
__device__ __forceinline__ uint32_t pack_bf16x2(float x, float y) {
    __nv_bfloat162 p = __floats2bfloat162_rn(x, y);
    return *(uint32_t*)&p;
}

// ======================= fp32 -> bf16 conversion pass =======================
__global__ void __launch_bounds__(256)
cvt_bf16(const float* __restrict__ src, __nv_bfloat16* __restrict__ dst)
{
    size_t i = ((size_t)blockIdx.x * 256 + threadIdx.x) * 4;
    float4 v = *(const float4*)(src + i);
    uint2 o;
    o.x = pack_bf16x2(v.x, v.y);
    o.y = pack_bf16x2(v.z, v.w);
    *(uint2*)(dst + i) = o;
}

// ======================= bf16 mma.sync GEMM: C = A * B^T =======================
// CTA 128x128, 8 warps (2x4), warp 64x32, KB=32, 3-stage cp.async, ldmatrix.x4.
// MODE 0: C = g_qkvb (bf16, NC=4096), epilogue = phi on q/k1/k2 groups
// MODE 1: C = g_x (fp32, NC=1024), epilogue = + residual R (h fp32)
#define KB 32
#define GITERS (DM / KB)            // 32
#define STG 3
#define RSH 40
#define STAGE_HALVES (128 * RSH)
#define GEMM_SMEM_BYTES (STG * 2 * STAGE_HALVES * 2)   // 61440

template<int MODE>
__global__ void __launch_bounds__(256, 2)
gemm_mma(const __nv_bfloat16* __restrict__ A, const __nv_bfloat16* __restrict__ Bm,
         const float* __restrict__ R, void* __restrict__ Cv, int NC)
{
    extern __shared__ __align__(16) char smraw[];
    __nv_bfloat16* smh = (__nv_bfloat16*)smraw;
    float* smf = (float*)smraw;
    const int tid = threadIdx.x;
    const int wid = tid >> 5, lane = tid & 31;
    const int wR = wid >> 2, wC = wid & 3;
    const int qr = lane >> 2, qc = lane & 3;
    const int m0 = blockIdx.y * 128, n0 = blockIdx.x * 128;

    float acc[4][4][4];
#pragma unroll
    for (int mt = 0; mt < 4; mt++)
#pragma unroll
        for (int nt = 0; nt < 4; nt++)
#pragma unroll
            for (int c = 0; c < 4; c++) acc[mt][nt][c] = 0.f;

    const int lrow = tid >> 2, lc = (tid & 3) * 8;

    auto issue = [&](int it) {
        if (it < GITERS) {
            const int s = it % STG;
            __nv_bfloat16* As = smh + s * 2 * STAGE_HALVES;
            __nv_bfloat16* Bs = As + STAGE_HALVES;
            const int k0 = it * KB;
            cp16(&As[lrow * RSH + lc],        A  + (size_t)(m0 + lrow) * DM + k0 + lc);
            cp16(&As[(lrow + 64) * RSH + lc], A  + (size_t)(m0 + lrow + 64) * DM + k0 + lc);
            cp16(&Bs[lrow * RSH + lc],        Bm + (size_t)(n0 + lrow) * DM + k0 + lc);
            cp16(&Bs[(lrow + 64) * RSH + lc], Bm + (size_t)(n0 + lrow + 64) * DM + k0 + lc);
        }
        asm volatile("cp.async.commit_group;" ::: "memory");
    };

    issue(0);
    issue(1);

    const uint32_t a_lane_off = ((wR * 64 + (lane & 15)) * RSH + ((lane >> 4) << 3)) * 2;
    const uint32_t b_lane_off = ((wC * 32 + ((lane >> 4) << 3) + (lane & 7)) * RSH +
                                 (((lane >> 3) & 1) << 3)) * 2;

#pragma unroll 1
    for (int it = 0; it < GITERS; ++it) {
        asm volatile("cp.async.wait_group 1;" ::: "memory");
        __syncthreads();
        issue(it + 2);

        const int s = it % STG;
        const uint32_t abase = smem_u32(smh + s * 2 * STAGE_HALVES) + a_lane_off;
        const uint32_t bbase = smem_u32(smh + s * 2 * STAGE_HALVES + STAGE_HALVES) + b_lane_off;

#pragma unroll
        for (int ks = 0; ks < 2; ks++) {
            uint32_t a[4][4], b[2][4];
#pragma unroll
            for (int mt = 0; mt < 4; mt++)
                LDSM4(a[mt][0], a[mt][1], a[mt][2], a[mt][3],
                      abase + mt * (16 * RSH * 2) + ks * 32);
#pragma unroll
            for (int nt2 = 0; nt2 < 2; nt2++)
                LDSM4(b[nt2][0], b[nt2][1], b[nt2][2], b[nt2][3],
                      bbase + nt2 * (16 * RSH * 2) + ks * 32);
#pragma unroll
            for (int mt = 0; mt < 4; mt++) {
                mma_bf16(acc[mt][0], a[mt], b[0][0], b[0][1]);
                mma_bf16(acc[mt][1], a[mt], b[0][2], b[0][3]);
                mma_bf16(acc[mt][2], a[mt], b[1][0], b[1][1]);
                mma_bf16(acc[mt][3], a[mt], b[1][2], b[1][3]);
            }
        }
    }
    asm volatile("cp.async.wait_group 0;" ::: "memory");
    __syncthreads();

    if (MODE == 0) {
        __nv_bfloat16* C = (__nv_bfloat16*)Cv;
        const int which = (n0 >> 7) & 3;   // 0=q,1=k1,2=k2,3=v
        float inv[4][2];
#pragma unroll
        for (int mt = 0; mt < 4; mt++) { inv[mt][0] = 1.f; inv[mt][1] = 1.f; }
        if (which < 3) {
#pragma unroll
            for (int mt = 0; mt < 4; mt++)
#pragma unroll
                for (int nt = 0; nt < 4; nt++)
#pragma unroll
                    for (int c = 0; c < 4; c++) {
                        float x = acc[mt][nt][c];
                        acc[mt][nt][c] = (x > 0.f) ? x + 1.f : __expf(x);
                    }
#pragma unroll
            for (int mt = 0; mt < 4; mt++)
#pragma unroll
                for (int hh = 0; hh < 2; hh++) {
                    float v = 0.f;
#pragma unroll
                    for (int nt = 0; nt < 4; nt++)
                        v += acc[mt][nt][hh * 2] + acc[mt][nt][hh * 2 + 1];
                    v += __shfl_xor_sync(0xffffffffu, v, 1);
                    v += __shfl_xor_sync(0xffffffffu, v, 2);
                    if (qc == 0)
                        smf[(wR * 64 + mt * 16 + hh * 8 + qr) * 4 + wC] = v;
                }
            __syncthreads();
#pragma unroll
            for (int mt = 0; mt < 4; mt++)
#pragma unroll
                for (int hh = 0; hh < 2; hh++) {
                    int row = wR * 64 + mt * 16 + hh * 8 + qr;
                    float s = smf[row * 4 + 0] + smf[row * 4 + 1] +
                              smf[row * 4 + 2] + smf[row * 4 + 3];
                    inv[mt][hh] = 1.f / s;
                }
        }
#pragma unroll
        for (int mt = 0; mt < 4; mt++)
#pragma unroll
            for (int hh = 0; hh < 2; hh++) {
                const int row = m0 + wR * 64 + mt * 16 + hh * 8 + qr;
                const float iv = inv[mt][hh];
#pragma unroll
                for (int nt = 0; nt < 4; nt++) {
                    uint32_t o = pack_bf16x2(acc[mt][nt][hh * 2] * iv,
                                             acc[mt][nt][hh * 2 + 1] * iv);
                    *(uint32_t*)(C + (size_t)row * NC + n0 + wC * 32 + nt * 8 + qc * 2) = o;
                }
            }
    } else {
        float* C = (float*)Cv;
#pragma unroll
        for (int mt = 0; mt < 4; mt++)
#pragma unroll
            for (int hh = 0; hh < 2; hh++) {
                const int row = m0 + wR * 64 + mt * 16 + hh * 8 + qr;
#pragma unroll
                for (int nt = 0; nt < 4; nt++) {
                    const int col = n0 + wC * 32 + nt * 8 + qc * 2;
                    float2 rr = *(const float2*)(R + (size_t)row * DM + col);
                    float2 o;
                    o.x = acc[mt][nt][hh * 2]     + rr.x;
                    o.y = acc[mt][nt][hh * 2 + 1] + rr.y;
                    *(float2*)(C + (size_t)row * NC + col) = o;
                }
            }
    }
}

// ======================= tensor-core dual causal linear attention =======================
// block = 256 thr (8 warps, 4(m) x 2(n)), t-tile = 64 rows; per s-tile <= t-tile:
// S1 = Q K1^T, S2 = Q K2^T (m16n8k16), P = pi*S1 + (1-pi)*S2 (causal mask) -> bf16 smem,
// O += P V. O stored * SCALE to g_lob bf16.
#define ARS 136                      // qkv tile row stride (halves)
#define PRS 72                       // P tile row stride (halves)
#define ATTN_SMEM_HALVES (4 * 64 * ARS + 64 * PRS)
#define ATTN_SMEM_BYTES (ATTN_SMEM_HALVES * 2)   // 78848

__global__ void __launch_bounds__(256, 2)
attn_mma(const float* __restrict__ pi0)
{
    extern __shared__ __align__(16) __nv_bfloat16 smh[];
    __nv_bfloat16* Qs  = smh;
    __nv_bfloat16* K1s = Qs  + 64 * ARS;
    __nv_bfloat16* K2s = K1s + 64 * ARS;
    __nv_bfloat16* Vs  = K2s + 64 * ARS;
    __nv_bfloat16* Ps  = Vs  + 64 * ARS;
    uint32_t* Pu = (uint32_t*)Ps;

    const int tid = threadIdx.x;
    const int wid = tid >> 5, lane = tid & 31;
    const int wm = wid >> 1, wn = wid & 1;
    const int qr = lane >> 2, qc = lane & 3;
    const int tt = blockIdx.x;
    const int bh = blockIdx.y;
    const int b  = bh >> 3, head = bh & 7;
    const int t0 = tt * 64;

    const int lrow = tid >> 2, lch = (tid & 3) * 4;   // 64 rows x 16 chunks(8h); 4 chunks/thread

    // load Q tile (full 64 x 128 halves)
#pragma unroll
    for (int c = 0; c < 4; c++) {
        int ch = lch + c;
        cp16(&Qs[lrow * ARS + ch * 8],
             g_qkvb + ((size_t)(t0 + lrow) * BSZ + b) * NQ + head * 512 + ch * 8);
    }
    asm volatile("cp.async.commit_group;" ::: "memory");

    const float pa = fminf(fmaxf(pi0[head * 256 + t0 + wm * 16 + qr], 0.f), 1.f);
    const float pb = fminf(fmaxf(pi0[head * 256 + t0 + wm * 16 + qr + 8], 0.f), 1.f);

    float o[8][4];
#pragma unroll
    for (int i = 0; i < 8; i++)
#pragma unroll
        for (int c = 0; c < 4; c++) o[i][c] = 0.f;

    // ldmatrix lane offsets
    const uint32_t qa_off = ((wm * 16 + (lane & 15)) * ARS + ((lane >> 4) << 3)) * 2;
    const uint32_t kb_off = ((wn * 32 + ((lane >> 4) << 3) + (lane & 7)) * ARS +
                             (((lane >> 3) & 1) << 3)) * 2;
    const uint32_t pa_off = ((wm * 16 + (lane & 15)) * PRS + ((lane >> 4) << 3)) * 2;
    const uint32_t vt_off = ((lane & 15) * ARS + wn * 64 + ((lane >> 4) << 3)) * 2;
    const uint32_t qbase = smem_u32(Qs), k1base = smem_u32(K1s), k2base = smem_u32(K2s);
    const uint32_t pbase = smem_u32(Ps), vbase = smem_u32(Vs);

#pragma unroll 1
    for (int st = 0; st <= tt; st++) {
        const int s0 = st * 64;
        if (st > 0) __syncthreads();   // prior PV done before overwriting K/V
        {
            size_t gb = ((size_t)(s0 + lrow) * BSZ + b) * NQ + head * 512;
#pragma unroll
            for (int c = 0; c < 4; c++) {
                int ch = lch + c;
                cp16(&K1s[lrow * ARS + ch * 8], g_qkvb + gb + 128 + ch * 8);
                cp16(&K2s[lrow * ARS + ch * 8], g_qkvb + gb + 256 + ch * 8);
                cp16(&Vs [lrow * ARS + ch * 8], g_qkvb + gb + 384 + ch * 8);
            }
        }
        asm volatile("cp.async.commit_group;" ::: "memory");
        asm volatile("cp.async.wait_group 0;" ::: "memory");
        __syncthreads();

        // ---- S phase ----
        float s1[4][4], s2[4][4];
#pragma unroll
        for (int nc = 0; nc < 4; nc++)
#pragma unroll
            for (int c = 0; c < 4; c++) { s1[nc][c] = 0.f; s2[nc][c] = 0.f; }

#pragma unroll
        for (int ks = 0; ks < 8; ks++) {
            uint32_t a[4], b1[2][4], b2[2][4];
            LDSM4(a[0], a[1], a[2], a[3], qbase + qa_off + ks * 32);
#pragma unroll
            for (int g = 0; g < 2; g++) {
                LDSM4(b1[g][0], b1[g][1], b1[g][2], b1[g][3],
                      k1base + kb_off + g * (16 * ARS * 2) + ks * 32);
                LDSM4(b2[g][0], b2[g][1], b2[g][2], b2[g][3],
                      k2base + kb_off + g * (16 * ARS * 2) + ks * 32);
            }
            mma_bf16(s1[0], a, b1[0][0], b1[0][1]);
            mma_bf16(s1[1], a, b1[0][2], b1[0][3]);
            mma_bf16(s1[2], a, b1[1][0], b1[1][1]);
            mma_bf16(s1[3], a, b1[1][2], b1[1][3]);
            mma_bf16(s2[0], a, b2[0][0], b2[0][1]);
            mma_bf16(s2[1], a, b2[0][2], b2[0][3]);
            mma_bf16(s2[2], a, b2[1][0], b2[1][1]);
            mma_bf16(s2[3], a, b2[1][2], b2[1][3]);
        }

        // ---- combine + mask -> P (bf16) ----
        const bool diag = (st == tt);
        const int tg0 = wm * 16 + qr, tg1 = tg0 + 8;
#pragma unroll
        for (int nc = 0; nc < 4; nc++) {
            const int c0 = wn * 32 + nc * 8 + qc * 2, c1 = c0 + 1;
            float v00 = s2[nc][0] + pa * (s1[nc][0] - s2[nc][0]);
            float v01 = s2[nc][1] + pa * (s1[nc][1] - s2[nc][1]);
            float v10 = s2[nc][2] + pb * (s1[nc][2] - s2[nc][2]);
            float v11 = s2[nc][3] + pb * (s1[nc][3] - s2[nc][3]);
            if (diag) {
                if (c0 > tg0) v00 = 0.f;
                if (c1 > tg0) v01 = 0.f;
                if (c0 > tg1) v10 = 0.f;
                if (c1 > tg1) v11 = 0.f;
            }
            Pu[tg0 * (PRS / 2) + (c0 >> 1)] = pack_bf16x2(v00, v01);
            Pu[tg1 * (PRS / 2) + (c0 >> 1)] = pack_bf16x2(v10, v11);
        }
        __syncthreads();

        // ---- PV phase: O(16 x 64dh per warp) += P(16x64s) V(64s x 64dh) ----
#pragma unroll
        for (int ks = 0; ks < 4; ks++) {
            uint32_t a[4];
            LDSM4(a[0], a[1], a[2], a[3], pbase + pa_off + ks * 32);
#pragma unroll
            for (int nc2 = 0; nc2 < 4; nc2++) {
                uint32_t b[4];
                LDSM4T(b[0], b[1], b[2], b[3],
                       vbase + vt_off + ks * (16 * ARS * 2) + nc2 * 32);
                mma_bf16(o[nc2 * 2],     a, b[0], b[1]);
                mma_bf16(o[nc2 * 2 + 1], a, b[2], b[3]);
            }
        }
    }

    // ---- store O * SCALE -> g_lob bf16 ----
#pragma unroll
    for (int i = 0; i < 8; i++) {
        const int dh = head * DH + wn * 64 + i * 8 + qc * 2;
        const int ta = t0 + wm * 16 + qr, tb2 = ta + 8;
        *(uint32_t*)(g_lob + ((size_t)ta * BSZ + b) * DM + dh) =
            pack_bf16x2(SCALE_F * o[i][0], SCALE_F * o[i][1]);
        *(uint32_t*)(g_lob + ((size_t)tb2 * BSZ + b) * DM + dh) =
            pack_bf16x2(SCALE_F * o[i][2], SCALE_F * o[i][3]);
    }
}

// ======================= LayerNorm =======================
__global__ void __launch_bounds__(256)
ln_kernel(const float* __restrict__ gamma, const float* __restrict__ beta,
          float* __restrict__ out)
{
    __shared__ float red[8];
    const int r = blockIdx.x, tid = threadIdx.x;
    const int lane = tid & 31, wid = tid >> 5;
    float4 v = *(const float4*)&g_x[(size_t)r * DM + tid * 4];
    float s = v.x + v.y + v.z + v.w;
#pragma unroll
    for (int o = 16; o > 0; o >>= 1) s += __shfl_xor_sync(0xffffffffu, s, o);
    if (lane == 0) red[wid] = s;
    __syncthreads();
    float tot = 0.f;
#pragma unroll
    for (int i = 0; i < 8; i++) tot += red[i];
    float mu = tot * (1.f / DM);
    float d0 = v.x - mu, d1 = v.y - mu, d2 = v.z - mu, d3 = v.w - mu;
    float sq = d0*d0 + d1*d1 + d2*d2 + d3*d3;
#pragma unroll
    for (int o = 16; o > 0; o >>= 1) sq += __shfl_xor_sync(0xffffffffu, sq, o);
    __syncthreads();
    if (lane == 0) red[wid] = sq;
    __syncthreads();
    float tot2 = 0.f;
#pragma unroll
    for (int i = 0; i < 8; i++) tot2 += red[i];
    float inv = rsqrtf(tot2 * (1.f / DM) + LN_EPS_F);
    float4 g = *(const float4*)&gamma[tid * 4];
    float4 bt = *(const float4*)&beta[tid * 4];
    float4 o;
    o.x = g.x * d0 * inv + bt.x;
    o.y = g.y * d1 * inv + bt.y;
    o.z = g.z * d2 * inv + bt.z;
    o.w = g.w * d3 * inv + bt.w;
    *(float4*)&out[(size_t)r * DM + tid * 4] = o;
}

// ======================= launch =======================
extern "C" void kernel_launch(void* const* d_in, const int* in_sizes, int n_in,
                              void* d_out, int out_size)
{
    const float* h     = (const float*)d_in[0];
    const float* Wqkv  = (const float*)d_in[1];
    const float* Wo    = (const float*)d_in[2];
    const float* pi0   = (const float*)d_in[3];
    const float* gamma = (const float*)d_in[4];
    const float* beta  = (const float*)d_in[5];
    float* out = (float*)d_out;

    float *p_x;
    __nv_bfloat16 *p_hb, *p_wqb, *p_wob, *p_lob, *p_qkvb;
    cudaGetSymbolAddress((void**)&p_x, g_x);
    cudaGetSymbolAddress((void**)&p_hb, g_hb);
    cudaGetSymbolAddress((void**)&p_wqb, g_wqb);
    cudaGetSymbolAddress((void**)&p_wob, g_wob);
    cudaGetSymbolAddress((void**)&p_lob, g_lob);
    cudaGetSymbolAddress((void**)&p_qkvb, g_qkvb);

    cudaFuncSetAttribute(gemm_mma<0>, cudaFuncAttributeMaxDynamicSharedMemorySize, GEMM_SMEM_BYTES);
    cudaFuncSetAttribute(gemm_mma<1>, cudaFuncAttributeMaxDynamicSharedMemorySize, GEMM_SMEM_BYTES);
    cudaFuncSetAttribute(attn_mma, cudaFuncAttributeMaxDynamicSharedMemorySize, ATTN_SMEM_BYTES);

    // 0. convert inputs to bf16
    cvt_bf16<<<(MROWS * DM) / 1024, 256>>>(h, p_hb);
    cvt_bf16<<<(NQ * DM) / 1024, 256>>>(Wqkv, p_wqb);
    cvt_bf16<<<(DM * DM) / 1024, 256>>>(Wo, p_wob);

    // 1. qkv = h @ Wqkv^T (bf16 mma), phi fused, bf16 out
    gemm_mma<0><<<dim3(NQ / 128, MROWS / 128), 256, GEMM_SMEM_BYTES>>>(p_hb, p_wqb, nullptr, p_qkvb, NQ);

    // 2. tensor-core dual causal linear attention -> g_lob (bf16)
    attn_mma<<<dim3(LSEQ / 64, BSZ * NH), 256, ATTN_SMEM_BYTES>>>(pi0);

    // 3. x = layer_out @ Wo^T + h (residual fused)
    gemm_mma<1><<<dim3(DM / 128, MROWS / 128), 256, GEMM_SMEM_BYTES>>>(p_lob, p_wob, h, p_x, DM);

    // 4. LayerNorm -> out
    ln_kernel<<<MROWS, 256>>>(gamma, beta, out);
}